// round 15
// baseline (speedup 1.0000x reference)
#include <cuda_runtime.h>
#include <cuda_fp16.h>
#include <cstdint>

// Bilinear attention B=8, S=2048, H=1024 fp32.
// GEMM1 (xw=x@W): 3xFP16-split mma (3 terms).
// GEMM2 (scores): 2 terms (Ah@Bh + Ah@Bm) -> logits carry ~8e-3 error; the
//   softmax kernel recomputes EXACT fp32 logits for the ~1-4 candidates per
//   row within 18 of the row max (one WARP per candidate -- no block-serial
//   latency chain), then does the softmax on corrected values.
// ctx = attn @ x via sparse fp32 gather (softmax rows are near-one-hot).

// ---------------- scratch (device globals; no allocation) ----------------
#define NBS (8ull * 2048ull * 1024ull)
#define NROWS (8 * 2048)
__device__ __half g_xh [NBS], g_xm [NBS];    // split x    [B,S,H]
__device__ __half g_wth[1024ull*1024ull], g_wtm[1024ull*1024ull];  // W^T split
__device__ __half g_xwh[NBS], g_xwm[NBS];    // split xw   [B,S,H]
__device__ int   g_sidx[(long long)NROWS * 2048];  // sparse col idx per row
__device__ float g_sval[(long long)NROWS * 2048];  // sparse attn values
__device__ int   g_nnz [NROWS];

#define SPARSE_THRESH 1e-9f
#define CAND_MARGIN   18.0f
#define MAX_CAND      64

// ---------------- helpers ----------------
__device__ __forceinline__ uint32_t smem_u32(const void* p) {
    uint32_t a;
    asm("{ .reg .u64 t; cvta.to.shared.u64 t, %1; cvt.u32.u64 %0, t; }" : "=r"(a) : "l"(p));
    return a;
}

#define CP_ASYNC16(dst, src) \
    asm volatile("cp.async.cg.shared.global [%0], [%1], 16;" :: "r"(dst), "l"(src) : "memory")
#define CP_COMMIT() asm volatile("cp.async.commit_group;" ::: "memory")
#define CP_WAIT(n)  asm volatile("cp.async.wait_group %0;" :: "n"(n) : "memory")

__device__ __forceinline__ void split16(float v, __half& h, __half& m) {
    h = __float2half_rn(v);
    m = __float2half_rn(v - __half2float(h));
}

__device__ __forceinline__ void mma16(float* c, const uint32_t* a, const uint32_t* b) {
    asm volatile(
        "mma.sync.aligned.m16n8k16.row.col.f32.f16.f16.f32 "
        "{%0,%1,%2,%3}, {%4,%5,%6,%7}, {%8,%9}, {%0,%1,%2,%3};"
        : "+f"(c[0]), "+f"(c[1]), "+f"(c[2]), "+f"(c[3])
        : "r"(a[0]), "r"(a[1]), "r"(a[2]), "r"(a[3]), "r"(b[0]), "r"(b[1]));
}

// ---------------- GEMM: C[m,n] = sum_k A[m,k]*B[n,k] ----------------
// CTA 128x256, K-chunk 32 (2 k16 steps), 2-stage cp.async, 256 threads.
// 8 warps (2M x 4N), warp tile 64x64 as two 64x32 N-halves.
// smem tiles: rows of 32 halfs at stride 40 -> conflict-free fragment LDS.
// TERMS=3: Ah@Bh + Ah@Bm + Am@Bh.   TERMS=2: Ah@Bh + Ah@Bm (no A-mid).
#define AST   40
#define ATB   (128 * AST * 2)   // 10240 B
#define BTB   (256 * AST * 2)   // 20480 B

template <int TERMS, bool CSPLIT>
__global__ __launch_bounds__(256, 1)
void gemm_fp16(const __half* __restrict__ Ahg, const __half* __restrict__ Amg,
               const __half* __restrict__ Bhg, const __half* __restrict__ Bmg,
               float* __restrict__ Cg, __half* __restrict__ Chg, __half* __restrict__ Cmg,
               int K, int N, long long sA, long long sB, long long sC)
{
    constexpr int T_AH = 0;
    constexpr int T_AM = ATB;                           // only if TERMS==3
    constexpr int T_BH = (TERMS >= 3) ? 2 * ATB : ATB;
    constexpr int T_BM = T_BH + BTB;
    constexpr int STG  = T_BM + BTB;                    // stage bytes

    extern __shared__ char smc[];
    const uint32_t sb = smem_u32(smc);

    const int tid  = threadIdx.x;
    const int wid  = tid >> 5;
    const int lane = tid & 31;
    const int g    = lane >> 2;
    const int tg   = lane & 3;
    const int wm   = (wid >> 2) * 64;
    const int wn   = (wid & 3) * 64;

    const long long aoff = blockIdx.z * sA + (long long)(blockIdx.y * 128) * K;
    const long long boff = blockIdx.z * sB + (long long)(blockIdx.x * 256) * K;
    const __half* Ah = Ahg + aoff;
    const __half* Am = (TERMS >= 3) ? (Amg + aoff) : nullptr;
    const __half* Bh = Bhg + boff;
    const __half* Bm = Bmg + boff;

    float acc[4][8][4];
#pragma unroll
    for (int mt = 0; mt < 4; ++mt)
#pragma unroll
        for (int nt = 0; nt < 8; ++nt)
#pragma unroll
            for (int q = 0; q < 4; ++q) acc[mt][nt][q] = 0.f;

    const int nc = K >> 5;

    auto stage_load = [&](int i, int s) {
        const int kt = i << 5;
        const uint32_t st = sb + (uint32_t)(s * STG);
#pragma unroll
        for (int p = 0; p < 2; ++p) {
            const int o = tid + p * 256;
            const int r = o >> 2;
            const int c = (o & 3) * 8;
            const uint32_t off = (uint32_t)(r * (AST * 2) + (o & 3) * 16);
            const long long gi = (long long)r * K + kt + c;
            CP_ASYNC16(st + T_AH + off, Ah + gi);
            if (TERMS >= 3) CP_ASYNC16(st + T_AM + off, Am + gi);
        }
#pragma unroll
        for (int p = 0; p < 4; ++p) {
            const int o = tid + p * 256;
            const int r = o >> 2;
            const int c = (o & 3) * 8;
            const uint32_t off = (uint32_t)(r * (AST * 2) + (o & 3) * 16);
            const long long gi = (long long)r * K + kt + c;
            CP_ASYNC16(st + T_BH + off, Bh + gi);
            CP_ASYNC16(st + T_BM + off, Bm + gi);
        }
    };

    stage_load(0, 0); CP_COMMIT();
    if (nc > 1) { stage_load(1, 1); }
    CP_COMMIT();

    for (int i = 0; i < nc; ++i) {
        if (i + 2 < nc) { CP_WAIT(1); } else { CP_WAIT(0); }
        __syncthreads();

        const char* stg = smc + (i & 1) * STG;
        const __half* AHs = (const __half*)(stg + T_AH);
        const __half* AMs = (const __half*)(stg + T_AM);
        const __half* BHs = (const __half*)(stg + T_BH);
        const __half* BMs = (const __half*)(stg + T_BM);

#pragma unroll
        for (int ks = 0; ks < 2; ++ks) {
            const int k0 = ks * 16;

            uint32_t ah[4][4], am[4][4];
#pragma unroll
            for (int mt = 0; mt < 4; ++mt) {
                const int r0 = wm + mt * 16 + g;
                const int i00 = r0 * AST + k0 + 2 * tg;
                const int i10 = (r0 + 8) * AST + k0 + 2 * tg;
                ah[mt][0] = *(const uint32_t*)(AHs + i00);
                ah[mt][1] = *(const uint32_t*)(AHs + i10);
                ah[mt][2] = *(const uint32_t*)(AHs + i00 + 8);
                ah[mt][3] = *(const uint32_t*)(AHs + i10 + 8);
                if (TERMS >= 3) {
                    am[mt][0] = *(const uint32_t*)(AMs + i00);
                    am[mt][1] = *(const uint32_t*)(AMs + i10);
                    am[mt][2] = *(const uint32_t*)(AMs + i00 + 8);
                    am[mt][3] = *(const uint32_t*)(AMs + i10 + 8);
                }
            }

#pragma unroll
            for (int h2 = 0; h2 < 2; ++h2) {
                uint32_t bh[4][2], bm[4][2];
#pragma unroll
                for (int nt = 0; nt < 4; ++nt) {
                    const int n0 = (wn + h2 * 32 + nt * 8 + g) * AST + k0 + 2 * tg;
                    bh[nt][0] = *(const uint32_t*)(BHs + n0);
                    bh[nt][1] = *(const uint32_t*)(BHs + n0 + 8);
                    bm[nt][0] = *(const uint32_t*)(BMs + n0);
                    bm[nt][1] = *(const uint32_t*)(BMs + n0 + 8);
                }
#pragma unroll
                for (int mt = 0; mt < 4; ++mt)
#pragma unroll
                    for (int nt = 0; nt < 4; ++nt)
                        mma16(acc[mt][h2 * 4 + nt], ah[mt], bh[nt]);
#pragma unroll
                for (int mt = 0; mt < 4; ++mt)
#pragma unroll
                    for (int nt = 0; nt < 4; ++nt)
                        mma16(acc[mt][h2 * 4 + nt], ah[mt], bm[nt]);
                if (TERMS >= 3) {
#pragma unroll
                    for (int mt = 0; mt < 4; ++mt)
#pragma unroll
                        for (int nt = 0; nt < 4; ++nt)
                            mma16(acc[mt][h2 * 4 + nt], am[mt], bh[nt]);
                }
            }
        }
        __syncthreads();
        if (i + 2 < nc) { stage_load(i + 2, i & 1); CP_COMMIT(); }
    }

    // ---- epilogue ----
    const long long crow = blockIdx.z * sC
                         + (long long)(blockIdx.y * 128 + wm) * N + blockIdx.x * 256 + wn;
    if (CSPLIT) {
        __half* Ch = Chg + crow;
        __half* Cm = Cmg + crow;
#pragma unroll
        for (int mt = 0; mt < 4; ++mt)
#pragma unroll
            for (int nt = 0; nt < 8; ++nt) {
                const long long r0 = (long long)(mt * 16 + g) * N + nt * 8 + 2 * tg;
                const long long r1 = r0 + 8LL * N;
                __half h0, m0, h1, m1, h2v, m2, h3, m3;
                split16(acc[mt][nt][0], h0, m0);
                split16(acc[mt][nt][1], h1, m1);
                split16(acc[mt][nt][2], h2v, m2);
                split16(acc[mt][nt][3], h3, m3);
                *(half2*)&Ch[r0] = __halves2half2(h0, h1);
                *(half2*)&Cm[r0] = __halves2half2(m0, m1);
                *(half2*)&Ch[r1] = __halves2half2(h2v, h3);
                *(half2*)&Cm[r1] = __halves2half2(m2, m3);
            }
    } else {
        float* C = Cg + crow;
#pragma unroll
        for (int mt = 0; mt < 4; ++mt)
#pragma unroll
            for (int nt = 0; nt < 8; ++nt) {
                const long long r0 = (long long)(mt * 16 + g) * N + nt * 8 + 2 * tg;
                const long long r1 = r0 + 8LL * N;
                *(float2*)&C[r0] = make_float2(acc[mt][nt][0], acc[mt][nt][1]);
                *(float2*)&C[r1] = make_float2(acc[mt][nt][2], acc[mt][nt][3]);
            }
    }
}

// ---------------- pre-split into two half arrays ----------------
__global__ __launch_bounds__(256)
void split_two(const float4* __restrict__ in, __half* __restrict__ oh,
               __half* __restrict__ om, long long n4)
{
    const long long i = (long long)blockIdx.x * blockDim.x + threadIdx.x;
    if (i >= n4) return;
    float4 v = in[i];
    __half h0, m0, h1, m1, h2, m2, h3, m3;
    split16(v.x, h0, m0); split16(v.y, h1, m1);
    split16(v.z, h2, m2); split16(v.w, h3, m3);
    *(half2*)&oh[4 * i]     = __halves2half2(h0, h1);
    *(half2*)&oh[4 * i + 2] = __halves2half2(h2, h3);
    *(half2*)&om[4 * i]     = __halves2half2(m0, m1);
    *(half2*)&om[4 * i + 2] = __halves2half2(m2, m3);
}

// ------- transpose + split W -------
__global__ __launch_bounds__(256)
void transpose_split2(const float* __restrict__ in, __half* __restrict__ outh,
                      __half* __restrict__ outm, int R, int C)
{
    __shared__ float t[32][33];
    const long long zo = (long long)blockIdx.z * R * C;
    in += zo; outh += zo; outm += zo;
    const int c0 = blockIdx.x * 32, r0 = blockIdx.y * 32;
#pragma unroll
    for (int dy = 0; dy < 32; dy += 8)
        t[threadIdx.y + dy][threadIdx.x] =
            in[(long long)(r0 + threadIdx.y + dy) * C + c0 + threadIdx.x];
    __syncthreads();
#pragma unroll
    for (int dy = 0; dy < 32; dy += 8) {
        __half h, m;
        split16(t[threadIdx.x][threadIdx.y + dy], h, m);
        const long long o = (long long)(c0 + threadIdx.y + dy) * R + r0 + threadIdx.x;
        outh[o] = h;
        outm[o] = m;
    }
}

// ------- softmax + warp-parallel exact candidate fix-up + sparse emit -----
// One block (256 thr) per row. Candidates (> max-18) get exact fp32 logits
// recomputed from the split xw / x arrays, ONE WARP PER CANDIDATE.
__global__ __launch_bounds__(256)
void softmax_fix(float* __restrict__ data,
                 const __half* __restrict__ xwh, const __half* __restrict__ xwm,
                 const __half* __restrict__ xh,  const __half* __restrict__ xm,
                 int* __restrict__ sidx, float* __restrict__ sval,
                 int* __restrict__ nnz)
{
    const int S = 2048;
    const long long row = blockIdx.x;
    const int b = (int)(row >> 11);
    float* p = data + row * S;
    const int tid = threadIdx.x;
    const int lane = tid & 31;
    const int wrp  = tid >> 5;

    float4 v0 = ((const float4*)p)[tid];
    float4 v1 = ((const float4*)p)[tid + 256];
    float vals[8] = {v0.x, v0.y, v0.z, v0.w, v1.x, v1.y, v1.z, v1.w};
    int   cols[8] = {4 * tid, 4 * tid + 1, 4 * tid + 2, 4 * tid + 3,
                     1024 + 4 * tid, 1024 + 4 * tid + 1,
                     1024 + 4 * tid + 2, 1024 + 4 * tid + 3};

    __shared__ float red[8];
    __shared__ int   cand[MAX_CAND];
    __shared__ float cexact[MAX_CAND];
    __shared__ int   ncand;

    // ---- provisional row max ----
    float m = vals[0];
#pragma unroll
    for (int q = 1; q < 8; ++q) m = fmaxf(m, vals[q]);
#pragma unroll
    for (int o = 16; o > 0; o >>= 1) m = fmaxf(m, __shfl_xor_sync(~0u, m, o));
    if (lane == 0) red[wrp] = m;
    if (tid == 0) ncand = 0;
    __syncthreads();
    {
        float t = (tid < 8) ? red[tid & 7] : -1e30f;
#pragma unroll
        for (int o = 4; o > 0; o >>= 1) t = fmaxf(t, __shfl_xor_sync(~0u, t, o));
        __syncthreads();
        if (tid == 0) red[0] = t;
        __syncthreads();
        m = red[0];
    }

    // ---- collect candidates (> max - margin) ----
    const float thresh = m - CAND_MARGIN;
#pragma unroll
    for (int q = 0; q < 8; ++q) {
        if (vals[q] > thresh) {
            int pos = atomicAdd(&ncand, 1);
            if (pos < MAX_CAND) cand[pos] = cols[q];
        }
    }
    __syncthreads();
    const int ncd = (ncand < MAX_CAND) ? ncand : MAX_CAND;

    // ---- exact fp32 recompute, ONE WARP PER CANDIDATE ----
    const half2* aqh2 = (const half2*)(xwh + row * 1024);
    const half2* aqm2 = (const half2*)(xwm + row * 1024);
    for (int ci = wrp; ci < ncd; ci += 8) {
        const int k = cand[ci];
        const long long ko = ((long long)b * 2048 + k) * 1024;
        const half2* bkh2 = (const half2*)(xh + ko);
        const half2* bkm2 = (const half2*)(xm + ko);
        float part = 0.f;
#pragma unroll
        for (int j = 0; j < 16; ++j) {
            const int idx = lane + j * 32;          // 0..511 half2
            float2 a_h = __half22float2(aqh2[idx]);
            float2 a_m = __half22float2(aqm2[idx]);
            float2 b_h = __half22float2(bkh2[idx]);
            float2 b_m = __half22float2(bkm2[idx]);
            part = fmaf(a_h.x + a_m.x, b_h.x + b_m.x, part);
            part = fmaf(a_h.y + a_m.y, b_h.y + b_m.y, part);
        }
#pragma unroll
        for (int o = 16; o > 0; o >>= 1) part += __shfl_xor_sync(~0u, part, o);
        if (lane == 0) cexact[ci] = part;
    }
    __syncthreads();

    // ---- replace candidate logits with exact values ----
    for (int ci = 0; ci < ncd; ++ci) {
        const int kc = cand[ci];
#pragma unroll
        for (int q = 0; q < 8; ++q)
            if (cols[q] == kc) vals[q] = cexact[ci];
    }

    // ---- final max ----
    m = vals[0];
#pragma unroll
    for (int q = 1; q < 8; ++q) m = fmaxf(m, vals[q]);
#pragma unroll
    for (int o = 16; o > 0; o >>= 1) m = fmaxf(m, __shfl_xor_sync(~0u, m, o));
    __syncthreads();
    if (lane == 0) red[wrp] = m;
    __syncthreads();
    {
        float t = (tid < 8) ? red[tid & 7] : -1e30f;
#pragma unroll
        for (int o = 4; o > 0; o >>= 1) t = fmaxf(t, __shfl_xor_sync(~0u, t, o));
        __syncthreads();
        if (tid == 0) red[0] = t;
        __syncthreads();
        m = red[0];
    }

    // ---- exp + sum ----
    float s = 0.f;
#pragma unroll
    for (int q = 0; q < 8; ++q) {
        vals[q] = __expf(vals[q] - m);
        s += vals[q];
    }
#pragma unroll
    for (int o = 16; o > 0; o >>= 1) s += __shfl_xor_sync(~0u, s, o);
    __syncthreads();
    if (lane == 0) red[wrp] = s;
    __syncthreads();
    {
        float t = (tid < 8) ? red[tid & 7] : 0.f;
#pragma unroll
        for (int o = 4; o > 0; o >>= 1) t += __shfl_xor_sync(~0u, t, o);
        __syncthreads();
        if (tid == 0) red[0] = t;
        __syncthreads();
        s = red[0];
    }

    const float inv = 1.0f / s;
#pragma unroll
    for (int q = 0; q < 8; ++q) vals[q] *= inv;

    ((float4*)p)[tid]       = make_float4(vals[0], vals[1], vals[2], vals[3]);
    ((float4*)p)[tid + 256] = make_float4(vals[4], vals[5], vals[6], vals[7]);

    // ---- deterministic compaction of values > SPARSE_THRESH ----
    int lc = 0;
#pragma unroll
    for (int q = 0; q < 8; ++q) lc += (vals[q] > SPARSE_THRESH) ? 1 : 0;

    int isum = lc;
#pragma unroll
    for (int o = 1; o < 32; o <<= 1) {
        int t = __shfl_up_sync(~0u, isum, o);
        if (lane >= o) isum += t;
    }
    __shared__ int wsum[8];
    if (lane == 31) wsum[wrp] = isum;
    __syncthreads();
    int wbase = 0;
#pragma unroll
    for (int i2 = 0; i2 < 8; ++i2) wbase += (i2 < wrp) ? wsum[i2] : 0;

    long long pos = row * (long long)S + wbase + (isum - lc);
#pragma unroll
    for (int q = 0; q < 8; ++q) {
        if (vals[q] > SPARSE_THRESH) {
            sidx[pos] = cols[q];
            sval[pos] = vals[q];
            pos++;
        }
    }
    if (tid == 255) nnz[row] = wbase + isum;
}

// ------- sparse ctx: one block (128 thr) per query row -------
__global__ __launch_bounds__(128)
void sparse_ctx(const float* __restrict__ x, const int* __restrict__ sidx,
                const float* __restrict__ sval, const int* __restrict__ nnz,
                float* __restrict__ ctx)
{
    const long long row = blockIdx.x;
    const int b = (int)(row >> 11);
    const int tid = threadIdx.x;
    const float* xb = x + (long long)b * 2048 * 1024;
    const long long base = row * 2048;
    const int n = nnz[row];

    float4 a0 = make_float4(0.f, 0.f, 0.f, 0.f);
    float4 a1 = make_float4(0.f, 0.f, 0.f, 0.f);

    for (int i = 0; i < n; ++i) {
        const int   k = sidx[base + i];
        const float v = sval[base + i];
        const float4* xr = (const float4*)(xb + (long long)k * 1024) + tid * 2;
        float4 p = xr[0], q = xr[1];
        a0.x += v * p.x; a0.y += v * p.y; a0.z += v * p.z; a0.w += v * p.w;
        a1.x += v * q.x; a1.y += v * q.y; a1.z += v * q.z; a1.w += v * q.w;
    }

    float4* out = (float4*)(ctx + row * 1024) + tid * 2;
    out[0] = a0;
    out[1] = a1;
}

// ---------------- launch ----------------
extern "C" void kernel_launch(void* const* d_in, const int* in_sizes, int n_in,
                              void* d_out, int out_size)
{
    const float* x = (const float*)d_in[0];   // [8,2048,1024]
    const float* w = (const float*)d_in[1];   // [1024,1024]
    float* ctx  = (float*)d_out;              // [8,2048,1024]
    float* attn = (float*)d_out + 16777216LL; // [8,2048,2048]

    __half *xh, *xm, *wth, *wtm, *xwh, *xwm;
    int *sidx, *nnz;
    float *sval;
    cudaGetSymbolAddress((void**)&xh,   g_xh);
    cudaGetSymbolAddress((void**)&xm,   g_xm);
    cudaGetSymbolAddress((void**)&wth,  g_wth);
    cudaGetSymbolAddress((void**)&wtm,  g_wtm);
    cudaGetSymbolAddress((void**)&xwh,  g_xwh);
    cudaGetSymbolAddress((void**)&xwm,  g_xwm);
    cudaGetSymbolAddress((void**)&sidx, g_sidx);
    cudaGetSymbolAddress((void**)&sval, g_sval);
    cudaGetSymbolAddress((void**)&nnz,  g_nnz);

    const int B = 8, S = 2048, H = 1024;

    const int SM3 = 2 * (2 * ATB + 2 * BTB);   // 122880
    const int SM2 = 2 * (ATB + 2 * BTB);       // 102400
    cudaFuncSetAttribute(gemm_fp16<3, true >, cudaFuncAttributeMaxDynamicSharedMemorySize, SM3);
    cudaFuncSetAttribute(gemm_fp16<2, false>, cudaFuncAttributeMaxDynamicSharedMemorySize, SM2);

    // pre-splits
    {
        long long n4 = (long long)B * S * H / 4;
        split_two<<<(unsigned)((n4 + 255) / 256), 256>>>((const float4*)x, xh, xm, n4);
    }
    transpose_split2<<<dim3(H / 32, H / 32, 1), dim3(32, 8)>>>(w, wth, wtm, H, H);

    // 1) xw = x @ W -> split xwh/xwm (3 terms)
    gemm_fp16<3, true><<<dim3(H / 256, (B * S) / 128, 1), 256, SM3>>>(
        xh, xm, wth, wtm, nullptr, xwh, xwm, H, H, 0, 0, 0);

    // 2) scores = xw @ x^T -> attn buffer (2 terms; candidates fixed later)
    gemm_fp16<2, false><<<dim3(S / 256, S / 128, B), 256, SM2>>>(
        xwh, xwm, xh, xm, attn, nullptr, nullptr, H, S,
        (long long)S * H, (long long)S * H, (long long)S * S);

    // 3) softmax + warp-parallel exact candidate fix-up; emit sparse list
    softmax_fix<<<B * S, 256>>>(attn, xwh, xwm, xh, xm, sidx, sval, nnz);

    // 4) ctx = sparse attn @ x, full fp32
    sparse_ctx<<<B * S, 128>>>(x, sidx, sval, nnz, ctx);
}

// round 16
// speedup vs baseline: 1.0992x; 1.0992x over previous
#include <cuda_runtime.h>
#include <cuda_fp16.h>
#include <cstdint>

// Bilinear attention B=8, S=2048, H=1024 fp32.
// GEMM1 (xw=x@W): 3xFP16-split mma (3 terms).
// GEMM2 (scores): 2 terms (Ah@Bh + Ah@Bm) -> logits carry ~8e-3 error.
// cand_fix (separate tiny kernel): per row, find max, recompute EXACT fp32
//   logits for candidates > max-18 (warp per candidate), write back.
// softmax_rows: R13's plain softmax + sparse emit (unchanged, proven 55us).
// sparse_ctx: ctx = attn @ x via sparse fp32 gather.

// ---------------- scratch (device globals; no allocation) ----------------
#define NBS (8ull * 2048ull * 1024ull)
#define NROWS (8 * 2048)
__device__ __half g_xh [NBS], g_xm [NBS];    // split x    [B,S,H]
__device__ __half g_wth[1024ull*1024ull], g_wtm[1024ull*1024ull];  // W^T split
__device__ __half g_xwh[NBS], g_xwm[NBS];    // split xw   [B,S,H]
__device__ int   g_sidx[(long long)NROWS * 2048];  // sparse col idx per row
__device__ float g_sval[(long long)NROWS * 2048];  // sparse attn values
__device__ int   g_nnz [NROWS];

#define SPARSE_THRESH 1e-9f
#define CAND_MARGIN   18.0f
#define MAX_CAND      64

// ---------------- helpers ----------------
__device__ __forceinline__ uint32_t smem_u32(const void* p) {
    uint32_t a;
    asm("{ .reg .u64 t; cvta.to.shared.u64 t, %1; cvt.u32.u64 %0, t; }" : "=r"(a) : "l"(p));
    return a;
}

#define CP_ASYNC16(dst, src) \
    asm volatile("cp.async.cg.shared.global [%0], [%1], 16;" :: "r"(dst), "l"(src) : "memory")
#define CP_COMMIT() asm volatile("cp.async.commit_group;" ::: "memory")
#define CP_WAIT(n)  asm volatile("cp.async.wait_group %0;" :: "n"(n) : "memory")

__device__ __forceinline__ void split16(float v, __half& h, __half& m) {
    h = __float2half_rn(v);
    m = __float2half_rn(v - __half2float(h));
}

__device__ __forceinline__ void mma16(float* c, const uint32_t* a, const uint32_t* b) {
    asm volatile(
        "mma.sync.aligned.m16n8k16.row.col.f32.f16.f16.f32 "
        "{%0,%1,%2,%3}, {%4,%5,%6,%7}, {%8,%9}, {%0,%1,%2,%3};"
        : "+f"(c[0]), "+f"(c[1]), "+f"(c[2]), "+f"(c[3])
        : "r"(a[0]), "r"(a[1]), "r"(a[2]), "r"(a[3]), "r"(b[0]), "r"(b[1]));
}

// ---------------- GEMM: C[m,n] = sum_k A[m,k]*B[n,k] ----------------
// CTA 128x256, K-chunk 32 (2 k16 steps), 2-stage cp.async, 256 threads.
// 8 warps (2M x 4N), warp tile 64x64 as two 64x32 N-halves.
// smem tiles: rows of 32 halfs at stride 40 -> conflict-free fragment LDS.
// TERMS=3: Ah@Bh + Ah@Bm + Am@Bh.   TERMS=2: Ah@Bh + Ah@Bm (no A-mid).
#define AST   40
#define ATB   (128 * AST * 2)   // 10240 B
#define BTB   (256 * AST * 2)   // 20480 B

template <int TERMS, bool CSPLIT>
__global__ __launch_bounds__(256, 1)
void gemm_fp16(const __half* __restrict__ Ahg, const __half* __restrict__ Amg,
               const __half* __restrict__ Bhg, const __half* __restrict__ Bmg,
               float* __restrict__ Cg, __half* __restrict__ Chg, __half* __restrict__ Cmg,
               int K, int N, long long sA, long long sB, long long sC)
{
    constexpr int T_AH = 0;
    constexpr int T_AM = ATB;                           // only if TERMS==3
    constexpr int T_BH = (TERMS >= 3) ? 2 * ATB : ATB;
    constexpr int T_BM = T_BH + BTB;
    constexpr int STG  = T_BM + BTB;                    // stage bytes

    extern __shared__ char smc[];
    const uint32_t sb = smem_u32(smc);

    const int tid  = threadIdx.x;
    const int wid  = tid >> 5;
    const int lane = tid & 31;
    const int g    = lane >> 2;
    const int tg   = lane & 3;
    const int wm   = (wid >> 2) * 64;
    const int wn   = (wid & 3) * 64;

    const long long aoff = blockIdx.z * sA + (long long)(blockIdx.y * 128) * K;
    const long long boff = blockIdx.z * sB + (long long)(blockIdx.x * 256) * K;
    const __half* Ah = Ahg + aoff;
    const __half* Am = (TERMS >= 3) ? (Amg + aoff) : nullptr;
    const __half* Bh = Bhg + boff;
    const __half* Bm = Bmg + boff;

    float acc[4][8][4];
#pragma unroll
    for (int mt = 0; mt < 4; ++mt)
#pragma unroll
        for (int nt = 0; nt < 8; ++nt)
#pragma unroll
            for (int q = 0; q < 4; ++q) acc[mt][nt][q] = 0.f;

    const int nc = K >> 5;

    auto stage_load = [&](int i, int s) {
        const int kt = i << 5;
        const uint32_t st = sb + (uint32_t)(s * STG);
#pragma unroll
        for (int p = 0; p < 2; ++p) {
            const int o = tid + p * 256;
            const int r = o >> 2;
            const int c = (o & 3) * 8;
            const uint32_t off = (uint32_t)(r * (AST * 2) + (o & 3) * 16);
            const long long gi = (long long)r * K + kt + c;
            CP_ASYNC16(st + T_AH + off, Ah + gi);
            if (TERMS >= 3) CP_ASYNC16(st + T_AM + off, Am + gi);
        }
#pragma unroll
        for (int p = 0; p < 4; ++p) {
            const int o = tid + p * 256;
            const int r = o >> 2;
            const int c = (o & 3) * 8;
            const uint32_t off = (uint32_t)(r * (AST * 2) + (o & 3) * 16);
            const long long gi = (long long)r * K + kt + c;
            CP_ASYNC16(st + T_BH + off, Bh + gi);
            CP_ASYNC16(st + T_BM + off, Bm + gi);
        }
    };

    stage_load(0, 0); CP_COMMIT();
    if (nc > 1) { stage_load(1, 1); }
    CP_COMMIT();

    for (int i = 0; i < nc; ++i) {
        if (i + 2 < nc) { CP_WAIT(1); } else { CP_WAIT(0); }
        __syncthreads();

        const char* stg = smc + (i & 1) * STG;
        const __half* AHs = (const __half*)(stg + T_AH);
        const __half* AMs = (const __half*)(stg + T_AM);
        const __half* BHs = (const __half*)(stg + T_BH);
        const __half* BMs = (const __half*)(stg + T_BM);

#pragma unroll
        for (int ks = 0; ks < 2; ++ks) {
            const int k0 = ks * 16;

            uint32_t ah[4][4], am[4][4];
#pragma unroll
            for (int mt = 0; mt < 4; ++mt) {
                const int r0 = wm + mt * 16 + g;
                const int i00 = r0 * AST + k0 + 2 * tg;
                const int i10 = (r0 + 8) * AST + k0 + 2 * tg;
                ah[mt][0] = *(const uint32_t*)(AHs + i00);
                ah[mt][1] = *(const uint32_t*)(AHs + i10);
                ah[mt][2] = *(const uint32_t*)(AHs + i00 + 8);
                ah[mt][3] = *(const uint32_t*)(AHs + i10 + 8);
                if (TERMS >= 3) {
                    am[mt][0] = *(const uint32_t*)(AMs + i00);
                    am[mt][1] = *(const uint32_t*)(AMs + i10);
                    am[mt][2] = *(const uint32_t*)(AMs + i00 + 8);
                    am[mt][3] = *(const uint32_t*)(AMs + i10 + 8);
                }
            }

#pragma unroll
            for (int h2 = 0; h2 < 2; ++h2) {
                uint32_t bh[4][2], bm[4][2];
#pragma unroll
                for (int nt = 0; nt < 4; ++nt) {
                    const int n0 = (wn + h2 * 32 + nt * 8 + g) * AST + k0 + 2 * tg;
                    bh[nt][0] = *(const uint32_t*)(BHs + n0);
                    bh[nt][1] = *(const uint32_t*)(BHs + n0 + 8);
                    bm[nt][0] = *(const uint32_t*)(BMs + n0);
                    bm[nt][1] = *(const uint32_t*)(BMs + n0 + 8);
                }
#pragma unroll
                for (int mt = 0; mt < 4; ++mt)
#pragma unroll
                    for (int nt = 0; nt < 4; ++nt)
                        mma16(acc[mt][h2 * 4 + nt], ah[mt], bh[nt]);
#pragma unroll
                for (int mt = 0; mt < 4; ++mt)
#pragma unroll
                    for (int nt = 0; nt < 4; ++nt)
                        mma16(acc[mt][h2 * 4 + nt], ah[mt], bm[nt]);
                if (TERMS >= 3) {
#pragma unroll
                    for (int mt = 0; mt < 4; ++mt)
#pragma unroll
                        for (int nt = 0; nt < 4; ++nt)
                            mma16(acc[mt][h2 * 4 + nt], am[mt], bh[nt]);
                }
            }
        }
        __syncthreads();
        if (i + 2 < nc) { stage_load(i + 2, i & 1); CP_COMMIT(); }
    }

    // ---- epilogue ----
    const long long crow = blockIdx.z * sC
                         + (long long)(blockIdx.y * 128 + wm) * N + blockIdx.x * 256 + wn;
    if (CSPLIT) {
        __half* Ch = Chg + crow;
        __half* Cm = Cmg + crow;
#pragma unroll
        for (int mt = 0; mt < 4; ++mt)
#pragma unroll
            for (int nt = 0; nt < 8; ++nt) {
                const long long r0 = (long long)(mt * 16 + g) * N + nt * 8 + 2 * tg;
                const long long r1 = r0 + 8LL * N;
                __half h0, m0, h1, m1, h2v, m2, h3, m3;
                split16(acc[mt][nt][0], h0, m0);
                split16(acc[mt][nt][1], h1, m1);
                split16(acc[mt][nt][2], h2v, m2);
                split16(acc[mt][nt][3], h3, m3);
                *(half2*)&Ch[r0] = __halves2half2(h0, h1);
                *(half2*)&Cm[r0] = __halves2half2(m0, m1);
                *(half2*)&Ch[r1] = __halves2half2(h2v, h3);
                *(half2*)&Cm[r1] = __halves2half2(m2, m3);
            }
    } else {
        float* C = Cg + crow;
#pragma unroll
        for (int mt = 0; mt < 4; ++mt)
#pragma unroll
            for (int nt = 0; nt < 8; ++nt) {
                const long long r0 = (long long)(mt * 16 + g) * N + nt * 8 + 2 * tg;
                const long long r1 = r0 + 8LL * N;
                *(float2*)&C[r0] = make_float2(acc[mt][nt][0], acc[mt][nt][1]);
                *(float2*)&C[r1] = make_float2(acc[mt][nt][2], acc[mt][nt][3]);
            }
    }
}

// ---------------- pre-split into two half arrays ----------------
__global__ __launch_bounds__(256)
void split_two(const float4* __restrict__ in, __half* __restrict__ oh,
               __half* __restrict__ om, long long n4)
{
    const long long i = (long long)blockIdx.x * blockDim.x + threadIdx.x;
    if (i >= n4) return;
    float4 v = in[i];
    __half h0, m0, h1, m1, h2, m2, h3, m3;
    split16(v.x, h0, m0); split16(v.y, h1, m1);
    split16(v.z, h2, m2); split16(v.w, h3, m3);
    *(half2*)&oh[4 * i]     = __halves2half2(h0, h1);
    *(half2*)&oh[4 * i + 2] = __halves2half2(h2, h3);
    *(half2*)&om[4 * i]     = __halves2half2(m0, m1);
    *(half2*)&om[4 * i + 2] = __halves2half2(m2, m3);
}

// ------- transpose + split W -------
__global__ __launch_bounds__(256)
void transpose_split2(const float* __restrict__ in, __half* __restrict__ outh,
                      __half* __restrict__ outm, int R, int C)
{
    __shared__ float t[32][33];
    const long long zo = (long long)blockIdx.z * R * C;
    in += zo; outh += zo; outm += zo;
    const int c0 = blockIdx.x * 32, r0 = blockIdx.y * 32;
#pragma unroll
    for (int dy = 0; dy < 32; dy += 8)
        t[threadIdx.y + dy][threadIdx.x] =
            in[(long long)(r0 + threadIdx.y + dy) * C + c0 + threadIdx.x];
    __syncthreads();
#pragma unroll
    for (int dy = 0; dy < 32; dy += 8) {
        __half h, m;
        split16(t[threadIdx.x][threadIdx.y + dy], h, m);
        const long long o = (long long)(c0 + threadIdx.y + dy) * R + r0 + threadIdx.x;
        outh[o] = h;
        outm[o] = m;
    }
}

// ------- cand_fix: per row, recompute exact logits of candidates --------
// One block (256 thr) per row. Finds row max, collects candidates
// (> max-18), recomputes them exactly in fp32 (one warp per candidate),
// writes corrected values back into the logits buffer. Carries no state
// into later phases (softmax is a separate, simple kernel).
__global__ __launch_bounds__(256)
void cand_fix(float* __restrict__ data,
              const __half* __restrict__ xwh, const __half* __restrict__ xwm,
              const __half* __restrict__ xh,  const __half* __restrict__ xm)
{
    const long long row = blockIdx.x;
    const int b = (int)(row >> 11);
    float* p = data + row * 2048;
    const int tid = threadIdx.x;
    const int lane = tid & 31;
    const int wrp  = tid >> 5;

    __shared__ float red[8];
    __shared__ int   cand[MAX_CAND];
    __shared__ int   ncand;
    if (tid == 0) ncand = 0;

    float4 v0 = ((const float4*)p)[tid];
    float4 v1 = ((const float4*)p)[tid + 256];

    float m = fmaxf(fmaxf(fmaxf(v0.x, v0.y), fmaxf(v0.z, v0.w)),
                    fmaxf(fmaxf(v1.x, v1.y), fmaxf(v1.z, v1.w)));
#pragma unroll
    for (int o = 16; o > 0; o >>= 1) m = fmaxf(m, __shfl_xor_sync(~0u, m, o));
    if (lane == 0) red[wrp] = m;
    __syncthreads();
    {
        float t = (tid < 8) ? red[tid & 7] : -1e30f;
#pragma unroll
        for (int o = 4; o > 0; o >>= 1) t = fmaxf(t, __shfl_xor_sync(~0u, t, o));
        __syncthreads();
        if (tid == 0) red[0] = t;
        __syncthreads();
        m = red[0];
    }

    const float thresh = m - CAND_MARGIN;
    float vv[8] = {v0.x, v0.y, v0.z, v0.w, v1.x, v1.y, v1.z, v1.w};
#pragma unroll
    for (int q = 0; q < 8; ++q) {
        if (vv[q] > thresh) {
            const int col = (q < 4) ? (4 * tid + q) : (1024 + 4 * tid + (q - 4));
            int pos = atomicAdd(&ncand, 1);
            if (pos < MAX_CAND) cand[pos] = col;
        }
    }
    __syncthreads();
    const int ncd = (ncand < MAX_CAND) ? ncand : MAX_CAND;

    // one warp per candidate: exact fp32 dot over 1024, write back
    const half2* aqh2 = (const half2*)(xwh + row * 1024);
    const half2* aqm2 = (const half2*)(xwm + row * 1024);
    for (int ci = wrp; ci < ncd; ci += 8) {
        const int k = cand[ci];
        const long long ko = ((long long)b * 2048 + k) * 1024;
        const half2* bkh2 = (const half2*)(xh + ko);
        const half2* bkm2 = (const half2*)(xm + ko);
        float part = 0.f;
#pragma unroll
        for (int j = 0; j < 16; ++j) {
            const int idx = lane + j * 32;
            float2 a_h = __half22float2(aqh2[idx]);
            float2 a_m = __half22float2(aqm2[idx]);
            float2 b_h = __half22float2(bkh2[idx]);
            float2 b_m = __half22float2(bkm2[idx]);
            part = fmaf(a_h.x + a_m.x, b_h.x + b_m.x, part);
            part = fmaf(a_h.y + a_m.y, b_h.y + b_m.y, part);
        }
#pragma unroll
        for (int o = 16; o > 0; o >>= 1) part += __shfl_xor_sync(~0u, part, o);
        if (lane == 0) p[k] = part;
    }
}

// ------- softmax over rows of 2048, in place; emits compact sparse list ---
// (identical to the R13 kernel that measured ~55us)
__global__ __launch_bounds__(256)
void softmax_rows(float* __restrict__ data, int* __restrict__ sidx,
                  float* __restrict__ sval, int* __restrict__ nnz)
{
    const int S = 2048;
    const long long row = blockIdx.x;
    float* p = data + row * S;
    const int tid = threadIdx.x;
    const int lane = tid & 31;
    const int wrp  = tid >> 5;

    float4 v0 = ((const float4*)p)[tid];
    float4 v1 = ((const float4*)p)[tid + 256];

    float m = fmaxf(fmaxf(fmaxf(v0.x, v0.y), fmaxf(v0.z, v0.w)),
                    fmaxf(fmaxf(v1.x, v1.y), fmaxf(v1.z, v1.w)));

    __shared__ float red[8];
#pragma unroll
    for (int o = 16; o > 0; o >>= 1) m = fmaxf(m, __shfl_xor_sync(~0u, m, o));
    if (lane == 0) red[wrp] = m;
    __syncthreads();
    {
        float t = (tid < 8) ? red[tid & 7] : -1e30f;
#pragma unroll
        for (int o = 4; o > 0; o >>= 1) t = fmaxf(t, __shfl_xor_sync(~0u, t, o));
        __syncthreads();
        if (tid == 0) red[0] = t;
        __syncthreads();
        m = red[0];
    }

    v0.x = __expf(v0.x - m); v0.y = __expf(v0.y - m);
    v0.z = __expf(v0.z - m); v0.w = __expf(v0.w - m);
    v1.x = __expf(v1.x - m); v1.y = __expf(v1.y - m);
    v1.z = __expf(v1.z - m); v1.w = __expf(v1.w - m);

    float s = v0.x + v0.y + v0.z + v0.w + v1.x + v1.y + v1.z + v1.w;
#pragma unroll
    for (int o = 16; o > 0; o >>= 1) s += __shfl_xor_sync(~0u, s, o);
    __syncthreads();
    if (lane == 0) red[wrp] = s;
    __syncthreads();
    {
        float t = (tid < 8) ? red[tid & 7] : 0.f;
#pragma unroll
        for (int o = 4; o > 0; o >>= 1) t += __shfl_xor_sync(~0u, t, o);
        __syncthreads();
        if (tid == 0) red[0] = t;
        __syncthreads();
        s = red[0];
    }

    const float inv = 1.0f / s;
    v0.x *= inv; v0.y *= inv; v0.z *= inv; v0.w *= inv;
    v1.x *= inv; v1.y *= inv; v1.z *= inv; v1.w *= inv;

    ((float4*)p)[tid]       = v0;
    ((float4*)p)[tid + 256] = v1;

    float vals[8] = {v0.x, v0.y, v0.z, v0.w, v1.x, v1.y, v1.z, v1.w};
    int   cols[8] = {4 * tid, 4 * tid + 1, 4 * tid + 2, 4 * tid + 3,
                     1024 + 4 * tid, 1024 + 4 * tid + 1,
                     1024 + 4 * tid + 2, 1024 + 4 * tid + 3};
    int lc = 0;
#pragma unroll
    for (int q = 0; q < 8; ++q) lc += (vals[q] > SPARSE_THRESH) ? 1 : 0;

    int isum = lc;
#pragma unroll
    for (int o = 1; o < 32; o <<= 1) {
        int t = __shfl_up_sync(~0u, isum, o);
        if (lane >= o) isum += t;
    }
    __shared__ int wsum[8];
    if (lane == 31) wsum[wrp] = isum;
    __syncthreads();
    int wbase = 0;
#pragma unroll
    for (int i2 = 0; i2 < 8; ++i2) wbase += (i2 < wrp) ? wsum[i2] : 0;

    long long pos = row * (long long)S + wbase + (isum - lc);
#pragma unroll
    for (int q = 0; q < 8; ++q) {
        if (vals[q] > SPARSE_THRESH) {
            sidx[pos] = cols[q];
            sval[pos] = vals[q];
            pos++;
        }
    }
    if (tid == 255) nnz[row] = wbase + isum;
}

// ------- sparse ctx: one block (128 thr) per query row -------
__global__ __launch_bounds__(128)
void sparse_ctx(const float* __restrict__ x, const int* __restrict__ sidx,
                const float* __restrict__ sval, const int* __restrict__ nnz,
                float* __restrict__ ctx)
{
    const long long row = blockIdx.x;
    const int b = (int)(row >> 11);
    const int tid = threadIdx.x;
    const float* xb = x + (long long)b * 2048 * 1024;
    const long long base = row * 2048;
    const int n = nnz[row];

    float4 a0 = make_float4(0.f, 0.f, 0.f, 0.f);
    float4 a1 = make_float4(0.f, 0.f, 0.f, 0.f);

    for (int i = 0; i < n; ++i) {
        const int   k = sidx[base + i];
        const float v = sval[base + i];
        const float4* xr = (const float4*)(xb + (long long)k * 1024) + tid * 2;
        float4 p = xr[0], q = xr[1];
        a0.x += v * p.x; a0.y += v * p.y; a0.z += v * p.z; a0.w += v * p.w;
        a1.x += v * q.x; a1.y += v * q.y; a1.z += v * q.z; a1.w += v * q.w;
    }

    float4* out = (float4*)(ctx + row * 1024) + tid * 2;
    out[0] = a0;
    out[1] = a1;
}

// ---------------- launch ----------------
extern "C" void kernel_launch(void* const* d_in, const int* in_sizes, int n_in,
                              void* d_out, int out_size)
{
    const float* x = (const float*)d_in[0];   // [8,2048,1024]
    const float* w = (const float*)d_in[1];   // [1024,1024]
    float* ctx  = (float*)d_out;              // [8,2048,1024]
    float* attn = (float*)d_out + 16777216LL; // [8,2048,2048]

    __half *xh, *xm, *wth, *wtm, *xwh, *xwm;
    int *sidx, *nnz;
    float *sval;
    cudaGetSymbolAddress((void**)&xh,   g_xh);
    cudaGetSymbolAddress((void**)&xm,   g_xm);
    cudaGetSymbolAddress((void**)&wth,  g_wth);
    cudaGetSymbolAddress((void**)&wtm,  g_wtm);
    cudaGetSymbolAddress((void**)&xwh,  g_xwh);
    cudaGetSymbolAddress((void**)&xwm,  g_xwm);
    cudaGetSymbolAddress((void**)&sidx, g_sidx);
    cudaGetSymbolAddress((void**)&sval, g_sval);
    cudaGetSymbolAddress((void**)&nnz,  g_nnz);

    const int B = 8, S = 2048, H = 1024;

    const int SM3 = 2 * (2 * ATB + 2 * BTB);   // 122880
    const int SM2 = 2 * (ATB + 2 * BTB);       // 102400
    cudaFuncSetAttribute(gemm_fp16<3, true >, cudaFuncAttributeMaxDynamicSharedMemorySize, SM3);
    cudaFuncSetAttribute(gemm_fp16<2, false>, cudaFuncAttributeMaxDynamicSharedMemorySize, SM2);

    // pre-splits
    {
        long long n4 = (long long)B * S * H / 4;
        split_two<<<(unsigned)((n4 + 255) / 256), 256>>>((const float4*)x, xh, xm, n4);
    }
    transpose_split2<<<dim3(H / 32, H / 32, 1), dim3(32, 8)>>>(w, wth, wtm, H, H);

    // 1) xw = x @ W -> split xwh/xwm (3 terms)
    gemm_fp16<3, true><<<dim3(H / 256, (B * S) / 128, 1), 256, SM3>>>(
        xh, xm, wth, wtm, nullptr, xwh, xwm, H, H, 0, 0, 0);

    // 2) scores = xw @ x^T -> attn buffer (2 terms)
    gemm_fp16<2, false><<<dim3(S / 256, S / 128, B), 256, SM2>>>(
        xwh, xwm, xh, xm, attn, nullptr, nullptr, H, S,
        (long long)S * H, (long long)S * H, (long long)S * S);

    // 3a) exact fix-up of near-max logits (separate light kernel)
    cand_fix<<<B * S, 256>>>(attn, xwh, xwm, xh, xm);

    // 3b) plain softmax + sparse emit (R13 kernel, unchanged)
    softmax_rows<<<B * S, 256>>>(attn, sidx, sval, nnz);

    // 4) ctx = sparse attn @ x, full fp32
    sparse_ctx<<<B * S, 128>>>(x, sidx, sval, nnz, ctx);
}

// round 17
// speedup vs baseline: 1.3277x; 1.2079x over previous
#include <cuda_runtime.h>
#include <cuda_fp16.h>
#include <cstdint>

// Bilinear attention B=8, S=2048, H=1024 fp32.
// GEMM1 (xw=x@W): 3xFP16-split mma (3 terms) -> split xwh/xwm.
// GEMM2 (scores): 1 term (Ah@Bh) -> logits carry ~1e-2 noise; harmless for
//   non-candidates (attn <= e^-18), and candidates (> max-18) are recomputed
//   EXACTLY in fp32 by cand_fix before the softmax.
// softmax_rows: plain softmax + sparse (idx,val) emit.
// sparse_ctx: ctx = attn @ x via sparse fp32 gather (rows near-one-hot).

// ---------------- scratch (device globals; no allocation) ----------------
#define NBS (8ull * 2048ull * 1024ull)
#define NROWS (8 * 2048)
__device__ __half g_xh [NBS], g_xm [NBS];    // split x    [B,S,H]
__device__ __half g_wth[1024ull*1024ull], g_wtm[1024ull*1024ull];  // W^T split
__device__ __half g_xwh[NBS], g_xwm[NBS];    // split xw   [B,S,H]
__device__ int   g_sidx[(long long)NROWS * 2048];  // sparse col idx per row
__device__ float g_sval[(long long)NROWS * 2048];  // sparse attn values
__device__ int   g_nnz [NROWS];

#define SPARSE_THRESH 1e-9f
#define CAND_MARGIN   18.0f
#define MAX_CAND      64

// ---------------- helpers ----------------
__device__ __forceinline__ uint32_t smem_u32(const void* p) {
    uint32_t a;
    asm("{ .reg .u64 t; cvta.to.shared.u64 t, %1; cvt.u32.u64 %0, t; }" : "=r"(a) : "l"(p));
    return a;
}

#define CP_ASYNC16(dst, src) \
    asm volatile("cp.async.cg.shared.global [%0], [%1], 16;" :: "r"(dst), "l"(src) : "memory")
#define CP_COMMIT() asm volatile("cp.async.commit_group;" ::: "memory")
#define CP_WAIT(n)  asm volatile("cp.async.wait_group %0;" :: "n"(n) : "memory")

__device__ __forceinline__ void split16(float v, __half& h, __half& m) {
    h = __float2half_rn(v);
    m = __float2half_rn(v - __half2float(h));
}

__device__ __forceinline__ void mma16(float* c, const uint32_t* a, const uint32_t* b) {
    asm volatile(
        "mma.sync.aligned.m16n8k16.row.col.f32.f16.f16.f32 "
        "{%0,%1,%2,%3}, {%4,%5,%6,%7}, {%8,%9}, {%0,%1,%2,%3};"
        : "+f"(c[0]), "+f"(c[1]), "+f"(c[2]), "+f"(c[3])
        : "r"(a[0]), "r"(a[1]), "r"(a[2]), "r"(a[3]), "r"(b[0]), "r"(b[1]));
}

// ---------------- GEMM: C[m,n] = sum_k A[m,k]*B[n,k] ----------------
// CTA 128x256, K-chunk 32 (2 k16 steps), 2-stage cp.async, 256 threads.
// 8 warps (2M x 4N), warp tile 64x64 as two 64x32 N-halves.
// smem tiles: rows of 32 halfs at stride 40 -> conflict-free fragment LDS.
// TERMS=3: Ah@Bh + Ah@Bm + Am@Bh.  TERMS=1: Ah@Bh only (no Am/Bm tiles).
#define AST   40
#define ATB   (128 * AST * 2)   // 10240 B
#define BTB   (256 * AST * 2)   // 20480 B

template <int TERMS, bool CSPLIT>
__global__ __launch_bounds__(256, 1)
void gemm_fp16(const __half* __restrict__ Ahg, const __half* __restrict__ Amg,
               const __half* __restrict__ Bhg, const __half* __restrict__ Bmg,
               float* __restrict__ Cg, __half* __restrict__ Chg, __half* __restrict__ Cmg,
               int K, int N, long long sA, long long sB, long long sC)
{
    constexpr int T_AH = 0;
    constexpr int T_AM = ATB;                            // only if TERMS==3
    constexpr int T_BH = (TERMS >= 3) ? 2 * ATB : ATB;
    constexpr int T_BM = T_BH + BTB;                     // only if TERMS>=2
    constexpr int STG  = (TERMS >= 3) ? (2 * ATB + 2 * BTB)
                       : (TERMS >= 2) ? (ATB + 2 * BTB)
                                      : (ATB + BTB);     // stage bytes

    extern __shared__ char smc[];
    const uint32_t sb = smem_u32(smc);

    const int tid  = threadIdx.x;
    const int wid  = tid >> 5;
    const int lane = tid & 31;
    const int g    = lane >> 2;
    const int tg   = lane & 3;
    const int wm   = (wid >> 2) * 64;
    const int wn   = (wid & 3) * 64;

    const long long aoff = blockIdx.z * sA + (long long)(blockIdx.y * 128) * K;
    const long long boff = blockIdx.z * sB + (long long)(blockIdx.x * 256) * K;
    const __half* Ah = Ahg + aoff;
    const __half* Am = (TERMS >= 3) ? (Amg + aoff) : nullptr;
    const __half* Bh = Bhg + boff;
    const __half* Bm = (TERMS >= 2) ? (Bmg + boff) : nullptr;

    float acc[4][8][4];
#pragma unroll
    for (int mt = 0; mt < 4; ++mt)
#pragma unroll
        for (int nt = 0; nt < 8; ++nt)
#pragma unroll
            for (int q = 0; q < 4; ++q) acc[mt][nt][q] = 0.f;

    const int nc = K >> 5;

    auto stage_load = [&](int i, int s) {
        const int kt = i << 5;
        const uint32_t st = sb + (uint32_t)(s * STG);
#pragma unroll
        for (int p = 0; p < 2; ++p) {
            const int o = tid + p * 256;
            const int r = o >> 2;
            const int c = (o & 3) * 8;
            const uint32_t off = (uint32_t)(r * (AST * 2) + (o & 3) * 16);
            const long long gi = (long long)r * K + kt + c;
            CP_ASYNC16(st + T_AH + off, Ah + gi);
            if (TERMS >= 3) CP_ASYNC16(st + T_AM + off, Am + gi);
        }
#pragma unroll
        for (int p = 0; p < 4; ++p) {
            const int o = tid + p * 256;
            const int r = o >> 2;
            const int c = (o & 3) * 8;
            const uint32_t off = (uint32_t)(r * (AST * 2) + (o & 3) * 16);
            const long long gi = (long long)r * K + kt + c;
            CP_ASYNC16(st + T_BH + off, Bh + gi);
            if (TERMS >= 2) CP_ASYNC16(st + T_BM + off, Bm + gi);
        }
    };

    stage_load(0, 0); CP_COMMIT();
    if (nc > 1) { stage_load(1, 1); }
    CP_COMMIT();

    for (int i = 0; i < nc; ++i) {
        if (i + 2 < nc) { CP_WAIT(1); } else { CP_WAIT(0); }
        __syncthreads();

        const char* stg = smc + (i & 1) * STG;
        const __half* AHs = (const __half*)(stg + T_AH);
        const __half* AMs = (const __half*)(stg + T_AM);
        const __half* BHs = (const __half*)(stg + T_BH);
        const __half* BMs = (const __half*)(stg + T_BM);

#pragma unroll
        for (int ks = 0; ks < 2; ++ks) {
            const int k0 = ks * 16;

            uint32_t ah[4][4], am[4][4];
#pragma unroll
            for (int mt = 0; mt < 4; ++mt) {
                const int r0 = wm + mt * 16 + g;
                const int i00 = r0 * AST + k0 + 2 * tg;
                const int i10 = (r0 + 8) * AST + k0 + 2 * tg;
                ah[mt][0] = *(const uint32_t*)(AHs + i00);
                ah[mt][1] = *(const uint32_t*)(AHs + i10);
                ah[mt][2] = *(const uint32_t*)(AHs + i00 + 8);
                ah[mt][3] = *(const uint32_t*)(AHs + i10 + 8);
                if (TERMS >= 3) {
                    am[mt][0] = *(const uint32_t*)(AMs + i00);
                    am[mt][1] = *(const uint32_t*)(AMs + i10);
                    am[mt][2] = *(const uint32_t*)(AMs + i00 + 8);
                    am[mt][3] = *(const uint32_t*)(AMs + i10 + 8);
                }
            }

#pragma unroll
            for (int h2 = 0; h2 < 2; ++h2) {
                uint32_t bh[4][2], bm[4][2];
#pragma unroll
                for (int nt = 0; nt < 4; ++nt) {
                    const int n0 = (wn + h2 * 32 + nt * 8 + g) * AST + k0 + 2 * tg;
                    bh[nt][0] = *(const uint32_t*)(BHs + n0);
                    bh[nt][1] = *(const uint32_t*)(BHs + n0 + 8);
                    if (TERMS >= 2) {
                        bm[nt][0] = *(const uint32_t*)(BMs + n0);
                        bm[nt][1] = *(const uint32_t*)(BMs + n0 + 8);
                    }
                }
#pragma unroll
                for (int mt = 0; mt < 4; ++mt)
#pragma unroll
                    for (int nt = 0; nt < 4; ++nt)
                        mma16(acc[mt][h2 * 4 + nt], ah[mt], bh[nt]);
                if (TERMS >= 2) {
#pragma unroll
                    for (int mt = 0; mt < 4; ++mt)
#pragma unroll
                        for (int nt = 0; nt < 4; ++nt)
                            mma16(acc[mt][h2 * 4 + nt], ah[mt], bm[nt]);
                }
                if (TERMS >= 3) {
#pragma unroll
                    for (int mt = 0; mt < 4; ++mt)
#pragma unroll
                        for (int nt = 0; nt < 4; ++nt)
                            mma16(acc[mt][h2 * 4 + nt], am[mt], bh[nt]);
                }
            }
        }
        __syncthreads();
        if (i + 2 < nc) { stage_load(i + 2, i & 1); CP_COMMIT(); }
    }

    // ---- epilogue ----
    const long long crow = blockIdx.z * sC
                         + (long long)(blockIdx.y * 128 + wm) * N + blockIdx.x * 256 + wn;
    if (CSPLIT) {
        __half* Ch = Chg + crow;
        __half* Cm = Cmg + crow;
#pragma unroll
        for (int mt = 0; mt < 4; ++mt)
#pragma unroll
            for (int nt = 0; nt < 8; ++nt) {
                const long long r0 = (long long)(mt * 16 + g) * N + nt * 8 + 2 * tg;
                const long long r1 = r0 + 8LL * N;
                __half h0, m0, h1, m1, h2v, m2, h3, m3;
                split16(acc[mt][nt][0], h0, m0);
                split16(acc[mt][nt][1], h1, m1);
                split16(acc[mt][nt][2], h2v, m2);
                split16(acc[mt][nt][3], h3, m3);
                *(half2*)&Ch[r0] = __halves2half2(h0, h1);
                *(half2*)&Cm[r0] = __halves2half2(m0, m1);
                *(half2*)&Ch[r1] = __halves2half2(h2v, h3);
                *(half2*)&Cm[r1] = __halves2half2(m2, m3);
            }
    } else {
        float* C = Cg + crow;
#pragma unroll
        for (int mt = 0; mt < 4; ++mt)
#pragma unroll
            for (int nt = 0; nt < 8; ++nt) {
                const long long r0 = (long long)(mt * 16 + g) * N + nt * 8 + 2 * tg;
                const long long r1 = r0 + 8LL * N;
                *(float2*)&C[r0] = make_float2(acc[mt][nt][0], acc[mt][nt][1]);
                *(float2*)&C[r1] = make_float2(acc[mt][nt][2], acc[mt][nt][3]);
            }
    }
}

// ---------------- pre-split into two half arrays ----------------
__global__ __launch_bounds__(256)
void split_two(const float4* __restrict__ in, __half* __restrict__ oh,
               __half* __restrict__ om, long long n4)
{
    const long long i = (long long)blockIdx.x * blockDim.x + threadIdx.x;
    if (i >= n4) return;
    float4 v = in[i];
    __half h0, m0, h1, m1, h2, m2, h3, m3;
    split16(v.x, h0, m0); split16(v.y, h1, m1);
    split16(v.z, h2, m2); split16(v.w, h3, m3);
    *(half2*)&oh[4 * i]     = __halves2half2(h0, h1);
    *(half2*)&oh[4 * i + 2] = __halves2half2(h2, h3);
    *(half2*)&om[4 * i]     = __halves2half2(m0, m1);
    *(half2*)&om[4 * i + 2] = __halves2half2(m2, m3);
}

// ------- transpose + split W -------
__global__ __launch_bounds__(256)
void transpose_split2(const float* __restrict__ in, __half* __restrict__ outh,
                      __half* __restrict__ outm, int R, int C)
{
    __shared__ float t[32][33];
    const long long zo = (long long)blockIdx.z * R * C;
    in += zo; outh += zo; outm += zo;
    const int c0 = blockIdx.x * 32, r0 = blockIdx.y * 32;
#pragma unroll
    for (int dy = 0; dy < 32; dy += 8)
        t[threadIdx.y + dy][threadIdx.x] =
            in[(long long)(r0 + threadIdx.y + dy) * C + c0 + threadIdx.x];
    __syncthreads();
#pragma unroll
    for (int dy = 0; dy < 32; dy += 8) {
        __half h, m;
        split16(t[threadIdx.x][threadIdx.y + dy], h, m);
        const long long o = (long long)(c0 + threadIdx.y + dy) * R + r0 + threadIdx.x;
        outh[o] = h;
        outm[o] = m;
    }
}

// ------- cand_fix: per row, recompute exact logits of candidates --------
__global__ __launch_bounds__(256)
void cand_fix(float* __restrict__ data,
              const __half* __restrict__ xwh, const __half* __restrict__ xwm,
              const __half* __restrict__ xh,  const __half* __restrict__ xm)
{
    const long long row = blockIdx.x;
    const int b = (int)(row >> 11);
    float* p = data + row * 2048;
    const int tid = threadIdx.x;
    const int lane = tid & 31;
    const int wrp  = tid >> 5;

    __shared__ float red[8];
    __shared__ int   cand[MAX_CAND];
    __shared__ int   ncand;
    if (tid == 0) ncand = 0;

    float4 v0 = ((const float4*)p)[tid];
    float4 v1 = ((const float4*)p)[tid + 256];

    float m = fmaxf(fmaxf(fmaxf(v0.x, v0.y), fmaxf(v0.z, v0.w)),
                    fmaxf(fmaxf(v1.x, v1.y), fmaxf(v1.z, v1.w)));
#pragma unroll
    for (int o = 16; o > 0; o >>= 1) m = fmaxf(m, __shfl_xor_sync(~0u, m, o));
    if (lane == 0) red[wrp] = m;
    __syncthreads();
    {
        float t = (tid < 8) ? red[tid & 7] : -1e30f;
#pragma unroll
        for (int o = 4; o > 0; o >>= 1) t = fmaxf(t, __shfl_xor_sync(~0u, t, o));
        __syncthreads();
        if (tid == 0) red[0] = t;
        __syncthreads();
        m = red[0];
    }

    const float thresh = m - CAND_MARGIN;
    float vv[8] = {v0.x, v0.y, v0.z, v0.w, v1.x, v1.y, v1.z, v1.w};
#pragma unroll
    for (int q = 0; q < 8; ++q) {
        if (vv[q] > thresh) {
            const int col = (q < 4) ? (4 * tid + q) : (1024 + 4 * tid + (q - 4));
            int pos = atomicAdd(&ncand, 1);
            if (pos < MAX_CAND) cand[pos] = col;
        }
    }
    __syncthreads();
    const int ncd = (ncand < MAX_CAND) ? ncand : MAX_CAND;

    const half2* aqh2 = (const half2*)(xwh + row * 1024);
    const half2* aqm2 = (const half2*)(xwm + row * 1024);
    for (int ci = wrp; ci < ncd; ci += 8) {
        const int k = cand[ci];
        const long long ko = ((long long)b * 2048 + k) * 1024;
        const half2* bkh2 = (const half2*)(xh + ko);
        const half2* bkm2 = (const half2*)(xm + ko);
        float part = 0.f;
#pragma unroll
        for (int j = 0; j < 16; ++j) {
            const int idx = lane + j * 32;
            float2 a_h = __half22float2(aqh2[idx]);
            float2 a_m = __half22float2(aqm2[idx]);
            float2 b_h = __half22float2(bkh2[idx]);
            float2 b_m = __half22float2(bkm2[idx]);
            part = fmaf(a_h.x + a_m.x, b_h.x + b_m.x, part);
            part = fmaf(a_h.y + a_m.y, b_h.y + b_m.y, part);
        }
#pragma unroll
        for (int o = 16; o > 0; o >>= 1) part += __shfl_xor_sync(~0u, part, o);
        if (lane == 0) p[k] = part;
    }
}

// ------- softmax over rows of 2048, in place; emits compact sparse list ---
__global__ __launch_bounds__(256)
void softmax_rows(float* __restrict__ data, int* __restrict__ sidx,
                  float* __restrict__ sval, int* __restrict__ nnz)
{
    const int S = 2048;
    const long long row = blockIdx.x;
    float* p = data + row * S;
    const int tid = threadIdx.x;
    const int lane = tid & 31;
    const int wrp  = tid >> 5;

    float4 v0 = ((const float4*)p)[tid];
    float4 v1 = ((const float4*)p)[tid + 256];

    float m = fmaxf(fmaxf(fmaxf(v0.x, v0.y), fmaxf(v0.z, v0.w)),
                    fmaxf(fmaxf(v1.x, v1.y), fmaxf(v1.z, v1.w)));

    __shared__ float red[8];
#pragma unroll
    for (int o = 16; o > 0; o >>= 1) m = fmaxf(m, __shfl_xor_sync(~0u, m, o));
    if (lane == 0) red[wrp] = m;
    __syncthreads();
    {
        float t = (tid < 8) ? red[tid & 7] : -1e30f;
#pragma unroll
        for (int o = 4; o > 0; o >>= 1) t = fmaxf(t, __shfl_xor_sync(~0u, t, o));
        __syncthreads();
        if (tid == 0) red[0] = t;
        __syncthreads();
        m = red[0];
    }

    v0.x = __expf(v0.x - m); v0.y = __expf(v0.y - m);
    v0.z = __expf(v0.z - m); v0.w = __expf(v0.w - m);
    v1.x = __expf(v1.x - m); v1.y = __expf(v1.y - m);
    v1.z = __expf(v1.z - m); v1.w = __expf(v1.w - m);

    float s = v0.x + v0.y + v0.z + v0.w + v1.x + v1.y + v1.z + v1.w;
#pragma unroll
    for (int o = 16; o > 0; o >>= 1) s += __shfl_xor_sync(~0u, s, o);
    __syncthreads();
    if (lane == 0) red[wrp] = s;
    __syncthreads();
    {
        float t = (tid < 8) ? red[tid & 7] : 0.f;
#pragma unroll
        for (int o = 4; o > 0; o >>= 1) t += __shfl_xor_sync(~0u, t, o);
        __syncthreads();
        if (tid == 0) red[0] = t;
        __syncthreads();
        s = red[0];
    }

    const float inv = 1.0f / s;
    v0.x *= inv; v0.y *= inv; v0.z *= inv; v0.w *= inv;
    v1.x *= inv; v1.y *= inv; v1.z *= inv; v1.w *= inv;

    ((float4*)p)[tid]       = v0;
    ((float4*)p)[tid + 256] = v1;

    float vals[8] = {v0.x, v0.y, v0.z, v0.w, v1.x, v1.y, v1.z, v1.w};
    int   cols[8] = {4 * tid, 4 * tid + 1, 4 * tid + 2, 4 * tid + 3,
                     1024 + 4 * tid, 1024 + 4 * tid + 1,
                     1024 + 4 * tid + 2, 1024 + 4 * tid + 3};
    int lc = 0;
#pragma unroll
    for (int q = 0; q < 8; ++q) lc += (vals[q] > SPARSE_THRESH) ? 1 : 0;

    int isum = lc;
#pragma unroll
    for (int o = 1; o < 32; o <<= 1) {
        int t = __shfl_up_sync(~0u, isum, o);
        if (lane >= o) isum += t;
    }
    __shared__ int wsum[8];
    if (lane == 31) wsum[wrp] = isum;
    __syncthreads();
    int wbase = 0;
#pragma unroll
    for (int i2 = 0; i2 < 8; ++i2) wbase += (i2 < wrp) ? wsum[i2] : 0;

    long long pos = row * (long long)S + wbase + (isum - lc);
#pragma unroll
    for (int q = 0; q < 8; ++q) {
        if (vals[q] > SPARSE_THRESH) {
            sidx[pos] = cols[q];
            sval[pos] = vals[q];
            pos++;
        }
    }
    if (tid == 255) nnz[row] = wbase + isum;
}

// ------- sparse ctx: one block (128 thr) per query row -------
__global__ __launch_bounds__(128)
void sparse_ctx(const float* __restrict__ x, const int* __restrict__ sidx,
                const float* __restrict__ sval, const int* __restrict__ nnz,
                float* __restrict__ ctx)
{
    const long long row = blockIdx.x;
    const int b = (int)(row >> 11);
    const int tid = threadIdx.x;
    const float* xb = x + (long long)b * 2048 * 1024;
    const long long base = row * 2048;
    const int n = nnz[row];

    float4 a0 = make_float4(0.f, 0.f, 0.f, 0.f);
    float4 a1 = make_float4(0.f, 0.f, 0.f, 0.f);

    for (int i = 0; i < n; ++i) {
        const int   k = sidx[base + i];
        const float v = sval[base + i];
        const float4* xr = (const float4*)(xb + (long long)k * 1024) + tid * 2;
        float4 p = xr[0], q = xr[1];
        a0.x += v * p.x; a0.y += v * p.y; a0.z += v * p.z; a0.w += v * p.w;
        a1.x += v * q.x; a1.y += v * q.y; a1.z += v * q.z; a1.w += v * q.w;
    }

    float4* out = (float4*)(ctx + row * 1024) + tid * 2;
    out[0] = a0;
    out[1] = a1;
}

// ---------------- launch ----------------
extern "C" void kernel_launch(void* const* d_in, const int* in_sizes, int n_in,
                              void* d_out, int out_size)
{
    const float* x = (const float*)d_in[0];   // [8,2048,1024]
    const float* w = (const float*)d_in[1];   // [1024,1024]
    float* ctx  = (float*)d_out;              // [8,2048,1024]
    float* attn = (float*)d_out + 16777216LL; // [8,2048,2048]

    __half *xh, *xm, *wth, *wtm, *xwh, *xwm;
    int *sidx, *nnz;
    float *sval;
    cudaGetSymbolAddress((void**)&xh,   g_xh);
    cudaGetSymbolAddress((void**)&xm,   g_xm);
    cudaGetSymbolAddress((void**)&wth,  g_wth);
    cudaGetSymbolAddress((void**)&wtm,  g_wtm);
    cudaGetSymbolAddress((void**)&xwh,  g_xwh);
    cudaGetSymbolAddress((void**)&xwm,  g_xwm);
    cudaGetSymbolAddress((void**)&sidx, g_sidx);
    cudaGetSymbolAddress((void**)&sval, g_sval);
    cudaGetSymbolAddress((void**)&nnz,  g_nnz);

    const int B = 8, S = 2048, H = 1024;

    const int SM3 = 2 * (2 * ATB + 2 * BTB);   // 122880
    const int SM1 = 2 * (ATB + BTB);           //  61440
    cudaFuncSetAttribute(gemm_fp16<3, true >, cudaFuncAttributeMaxDynamicSharedMemorySize, SM3);
    cudaFuncSetAttribute(gemm_fp16<1, false>, cudaFuncAttributeMaxDynamicSharedMemorySize, SM1);

    // pre-splits
    {
        long long n4 = (long long)B * S * H / 4;
        split_two<<<(unsigned)((n4 + 255) / 256), 256>>>((const float4*)x, xh, xm, n4);
    }
    transpose_split2<<<dim3(H / 32, H / 32, 1), dim3(32, 8)>>>(w, wth, wtm, H, H);

    // 1) xw = x @ W -> split xwh/xwm (3 terms)
    gemm_fp16<3, true><<<dim3(H / 256, (B * S) / 128, 1), 256, SM3>>>(
        xh, xm, wth, wtm, nullptr, xwh, xwm, H, H, 0, 0, 0);

    // 2) scores = xw @ x^T -> attn buffer (1 term; candidates fixed next)
    gemm_fp16<1, false><<<dim3(S / 256, S / 128, B), 256, SM1>>>(
        xwh, nullptr, xh, nullptr, attn, nullptr, nullptr, H, S,
        (long long)S * H, (long long)S * H, (long long)S * S);

    // 3a) exact fix-up of near-max logits
    cand_fix<<<B * S, 256>>>(attn, xwh, xwm, xh, xm);

    // 3b) plain softmax + sparse emit
    softmax_rows<<<B * S, 256>>>(attn, sidx, sval, nnz);

    // 4) ctx = sparse attn @ x, full fp32
    sparse_ctx<<<B * S, 128>>>(x, sidx, sval, nnz, ctx);
}